// round 2
// baseline (speedup 1.0000x reference)
#include <cuda_runtime.h>

#define R        128
#define R2       (R*R)
#define R3       (R*R*R)
#define BATCH    2
#define NV       7700
#define NSURF    6890
#define NT       30000
#define EPS_W    0.001f
#define INV_R    (1.0f/128.0f)

// Scratch: {wsum, sem0, sem1, sem2} packed per voxel, plus occupancy.
__device__ float4 g_acc[BATCH * R3];   // 64 MB
__device__ float  g_occ[BATCH * R3];   // 16 MB

__device__ __forceinline__ float3 ld3(const float* __restrict__ p) {
    return make_float3(p[0], p[1], p[2]);
}

__global__ void init_kernel() {
    int i = blockIdx.x * blockDim.x + threadIdx.x;
    if (i < BATCH * R3) {
        g_acc[i] = make_float4(EPS_W, 0.f, 0.f, 0.f);
        g_occ[i] = 0.f;
    }
}

// One thread per (batch, tet, window-voxel). 125 = 5^3 window.
__global__ void tet_kernel(const float* __restrict__ verts,
                           const int*   __restrict__ tets) {
    int idx = blockIdx.x * blockDim.x + threadIdx.x;
    const int TOTAL = BATCH * NT * 125;
    if (idx >= TOTAL) return;

    int v = idx % 125;
    int t = (idx / 125) % NT;
    int b = idx / (125 * NT);

    int i0 = tets[t * 4 + 0];
    int i1 = tets[t * 4 + 1];
    int i2 = tets[t * 4 + 2];
    int i3 = tets[t * 4 + 3];

    const float* vb = verts + (size_t)b * NV * 3;
    float3 a  = ld3(vb + (size_t)i0 * 3);
    float3 p1 = ld3(vb + (size_t)i1 * 3);
    float3 p2 = ld3(vb + (size_t)i2 * 3);
    float3 p3 = ld3(vb + (size_t)i3 * 3);

    float3 e1 = make_float3(p1.x - a.x, p1.y - a.y, p1.z - a.z);
    float3 e2 = make_float3(p2.x - a.x, p2.y - a.y, p2.z - a.z);
    float3 e3 = make_float3(p3.x - a.x, p3.y - a.y, p3.z - a.z);

    float3 c23 = make_float3(e2.y * e3.z - e2.z * e3.y,
                             e2.z * e3.x - e2.x * e3.z,
                             e2.x * e3.y - e2.y * e3.x);
    float vol6 = e1.x * c23.x + e1.y * c23.y + e1.z * c23.z;
    if (fabsf(vol6) <= 1e-12f) return;   // inside requires |vol6| > 1e-12
    float iv = 1.0f / vol6;

    int ax = (int)floorf(fminf(fminf(a.x, p1.x), fminf(p2.x, p3.x)) * (float)R);
    int ay = (int)floorf(fminf(fminf(a.y, p1.y), fminf(p2.y, p3.y)) * (float)R);
    int az = (int)floorf(fminf(fminf(a.z, p1.z), fminf(p2.z, p3.z)) * (float)R);

    int vx = ax + (v / 25);
    int vy = ay + ((v / 5) % 5);
    int vz = az + (v % 5);
    if ((unsigned)vx >= R || (unsigned)vy >= R || (unsigned)vz >= R) return;

    float3 p = make_float3(((float)vx + 0.5f) * INV_R - a.x,
                           ((float)vy + 0.5f) * INV_R - a.y,
                           ((float)vz + 0.5f) * INV_R - a.z);

    float l1 = (p.x * c23.x + p.y * c23.y + p.z * c23.z) * iv;

    float3 pxe3 = make_float3(p.y * e3.z - p.z * e3.y,
                              p.z * e3.x - p.x * e3.z,
                              p.x * e3.y - p.y * e3.x);
    float l2 = (pxe3.x * e1.x + pxe3.y * e1.y + pxe3.z * e1.z) * iv;

    float3 e2xp = make_float3(e2.y * p.z - e2.z * p.y,
                              e2.z * p.x - e2.x * p.z,
                              e2.x * p.y - e2.y * p.x);
    float l3 = (e2xp.x * e1.x + e2xp.y * e1.y + e2xp.z * e1.z) * iv;

    if (l1 >= 0.f && l2 >= 0.f && l3 >= 0.f && (l1 + l2 + l3) <= 1.0f) {
        int lin = ((b * R + vz) * R + vy) * R + vx;
        g_occ[lin] = 1.0f;   // scatter-max of {0,1} -> plain store
    }
}

// One thread per (batch, surface-vertex, splat-offset). 343 = 7^3 window.
__global__ void splat_kernel(const float* __restrict__ verts,
                             const float* __restrict__ code) {
    int idx = blockIdx.x * blockDim.x + threadIdx.x;
    const int TOTAL = BATCH * NSURF * 343;
    if (idx >= TOTAL) return;

    int o = idx % 343;
    int s = (idx / 343) % NSURF;
    int b = idx / (343 * NSURF);

    float3 vs = ld3(verts + ((size_t)b * NV + s) * 3);

    int bx = (int)floorf(vs.x * (float)R);
    int by = (int)floorf(vs.y * (float)R);
    int bz = (int)floorf(vs.z * (float)R);

    int vx = bx + (o / 49) - 3;
    int vy = by + ((o / 7) % 7) - 3;
    int vz = bz + (o % 7) - 3;
    if ((unsigned)vx >= R || (unsigned)vy >= R || (unsigned)vz >= R) return;

    float dx = ((float)vx + 0.5f) * INV_R - vs.x;
    float dy = ((float)vy + 0.5f) * INV_R - vs.y;
    float dz = ((float)vz + 0.5f) * INV_R - vs.z;
    float d2 = dx * dx + dy * dy + dz * dz;
    float w  = __expf(-d2 * 200.0f);   // 1/(2*sigma^2), sigma=0.05

    float3 vc = ld3(code + ((size_t)b * NSURF + s) * 3);

    int lin = ((b * R + vz) * R + vy) * R + vx;
    float4* ptr = &g_acc[lin];
    // One vector reduction: {wsum += w, sem += w*code}
    asm volatile("red.global.add.v4.f32 [%0], {%1, %2, %3, %4};"
                 :: "l"(ptr), "f"(w), "f"(w * vc.x), "f"(w * vc.y), "f"(w * vc.z)
                 : "memory");
}

// out layout: (B, 3, Z, Y, X); lin-within-batch is already z*R2 + y*R + x.
__global__ void finalize_kernel(float* __restrict__ out) {
    int i = blockIdx.x * blockDim.x + threadIdx.x;
    if (i >= BATCH * R3) return;
    int b = i / R3;
    int l = i - b * R3;

    float4 acc = g_acc[i];
    float  occ = g_occ[i];
    float  sc  = occ / acc.x;   // occ in {0,1}; wsum >= EPS_W > 0

    float* ob = out + (size_t)b * 3 * R3 + l;
    ob[0]        = acc.y * sc;
    ob[R3]       = acc.z * sc;
    ob[2 * R3]   = acc.w * sc;
}

extern "C" void kernel_launch(void* const* d_in, const int* in_sizes, int n_in,
                              void* d_out, int out_size) {
    const float* verts = (const float*)d_in[0];   // smpl_vertices (B, NV, 3)
    const float* code  = (const float*)d_in[1];   // vertex_code   (B, NSURF, 3)
    // d_in[2] face_indices: unused (dead code in reference)
    const int*   tets  = (const int*)d_in[3];     // tet_indices   (NT, 4)
    float*       out   = (float*)d_out;

    const int T = 256;
    init_kernel<<<(BATCH * R3 + T - 1) / T, T>>>();
    tet_kernel<<<(BATCH * NT * 125 + T - 1) / T, T>>>(verts, tets);
    splat_kernel<<<(BATCH * NSURF * 343 + T - 1) / T, T>>>(verts, code);
    finalize_kernel<<<(BATCH * R3 + T - 1) / T, T>>>(out);
}

// round 12
// speedup vs baseline: 1.1187x; 1.1187x over previous
#include <cuda_runtime.h>
#include <cstdint>

#define R        128
#define R2       (R*R)
#define R3       (R*R*R)
#define BATCH    2
#define NV       7700
#define NSURF    6890
#define NT       30000
#define EPS_W    0.001f
#define INV_R    (1.0f/128.0f)

// Scratch: {wsum, sem0, sem1, sem2} packed per voxel (zero-init; EPS_W added in finalize).
__device__ float4  g_acc[BATCH * R3];      // 64 MB
__device__ uint8_t g_occ[BATCH * R3];      // 4 MB
// Per-tet precomputed data: 5 float4 per (b,t):
// [0]={a.xyz, iv} [1]={c23.xyz, packed_anchor} [2]={e1.xyz,0} [3]={e2.xyz,0} [4]={e3.xyz,0}
__device__ float4  g_tet[BATCH * NT * 5];  // 4.8 MB

__device__ __forceinline__ float3 ld3(const float* __restrict__ p) {
    return make_float3(p[0], p[1], p[2]);
}

// ---------------------------------------------------------------- tet setup
__global__ void tet_setup_kernel(const float* __restrict__ verts,
                                 const int*   __restrict__ tets) {
    int idx = blockIdx.x * blockDim.x + threadIdx.x;
    if (idx >= BATCH * NT) return;
    int t = idx % NT;
    int b = idx / NT;

    int i0 = tets[t * 4 + 0];
    int i1 = tets[t * 4 + 1];
    int i2 = tets[t * 4 + 2];
    int i3 = tets[t * 4 + 3];

    const float* vb = verts + (size_t)b * NV * 3;
    float3 a  = ld3(vb + (size_t)i0 * 3);
    float3 p1 = ld3(vb + (size_t)i1 * 3);
    float3 p2 = ld3(vb + (size_t)i2 * 3);
    float3 p3 = ld3(vb + (size_t)i3 * 3);

    float3 e1 = make_float3(p1.x - a.x, p1.y - a.y, p1.z - a.z);
    float3 e2 = make_float3(p2.x - a.x, p2.y - a.y, p2.z - a.z);
    float3 e3 = make_float3(p3.x - a.x, p3.y - a.y, p3.z - a.z);

    float3 c23 = make_float3(e2.y * e3.z - e2.z * e3.y,
                             e2.z * e3.x - e2.x * e3.z,
                             e2.x * e3.y - e2.y * e3.x);
    float vol6 = e1.x * c23.x + e1.y * c23.y + e1.z * c23.z;
    bool valid = fabsf(vol6) > 1e-12f;
    float iv = valid ? (1.0f / vol6) : 0.0f;

    unsigned pk;
    if (valid) {
        int ax = (int)floorf(fminf(fminf(a.x, p1.x), fminf(p2.x, p3.x)) * (float)R);
        int ay = (int)floorf(fminf(fminf(a.y, p1.y), fminf(p2.y, p3.y)) * (float)R);
        int az = (int)floorf(fminf(fminf(a.z, p1.z), fminf(p2.z, p3.z)) * (float)R);
        // Inputs are uniform in [0,1): anchors fit in [0,127]. Clamp defensively to u8.
        pk = ((unsigned)(ax & 0xFF)) | ((unsigned)(ay & 0xFF) << 8) | ((unsigned)(az & 0xFF) << 16);
    } else {
        pk = 0xFFFFFFu;  // anchor 255,255,255 -> every window voxel fails bounds
    }

    float4* o = &g_tet[(size_t)idx * 5];
    o[0] = make_float4(a.x, a.y, a.z, iv);
    o[1] = make_float4(c23.x, c23.y, c23.z, __uint_as_float(pk));
    o[2] = make_float4(e1.x, e1.y, e1.z, 0.f);
    o[3] = make_float4(e2.x, e2.y, e2.z, 0.f);
    o[4] = make_float4(e3.x, e3.y, e3.z, 0.f);
}

// ---------------------------------------------------------------- tet test
// One thread per (batch*tet, window-voxel). 125 = 5^3 window.
__global__ void tet_test_kernel() {
    int idx = blockIdx.x * blockDim.x + threadIdx.x;
    const int TOTAL = BATCH * NT * 125;
    if (idx >= TOTAL) return;

    int v  = idx % 125;
    int bt = idx / 125;
    int b  = bt / NT;

    const float4* d = &g_tet[(size_t)bt * 5];
    float4 f0 = d[0];   // a, iv
    float4 f1 = d[1];   // c23, anchor
    float4 f2 = d[2];   // e1
    float4 f3 = d[3];   // e2
    float4 f4 = d[4];   // e3

    unsigned pk = __float_as_uint(f1.w);
    int vx = (int)(pk & 0xFF)         + (v / 25);
    int vy = (int)((pk >> 8) & 0xFF)  + ((v / 5) % 5);
    int vz = (int)((pk >> 16) & 0xFF) + (v % 5);
    if ((unsigned)vx >= R || (unsigned)vy >= R || (unsigned)vz >= R) return;

    float iv = f0.w;
    float3 p = make_float3(((float)vx + 0.5f) * INV_R - f0.x,
                           ((float)vy + 0.5f) * INV_R - f0.y,
                           ((float)vz + 0.5f) * INV_R - f0.z);

    float l1 = (p.x * f1.x + p.y * f1.y + p.z * f1.z) * iv;

    // (p x e3) . e1
    float l2 = ((p.y * f4.z - p.z * f4.y) * f2.x +
                (p.z * f4.x - p.x * f4.z) * f2.y +
                (p.x * f4.y - p.y * f4.x) * f2.z) * iv;

    // (e2 x p) . e1
    float l3 = ((f3.y * p.z - f3.z * p.y) * f2.x +
                (f3.z * p.x - f3.x * p.z) * f2.y +
                (f3.x * p.y - f3.y * p.x) * f2.z) * iv;

    if (l1 >= 0.f && l2 >= 0.f && l3 >= 0.f && (l1 + l2 + l3) <= 1.0f) {
        int lin = ((b * R + vz) * R + vy) * R + vx;
        g_occ[lin] = 1;   // scatter-max of {0,1} -> plain store
    }
}

// ---------------------------------------------------------------- splat
// One WARP per (batch, surface-vertex). Separable Gaussian: w = wx*wy*wz.
__global__ void splat_kernel(const float* __restrict__ verts,
                             const float* __restrict__ code) {
    int gw   = (blockIdx.x * blockDim.x + threadIdx.x) >> 5;
    int lane = threadIdx.x & 31;
    if (gw >= BATCH * NSURF) return;
    int s = gw % NSURF;
    int b = gw / NSURF;

    float3 vs = ld3(verts + ((size_t)b * NV + s) * 3);
    float3 vc = ld3(code  + ((size_t)b * NSURF + s) * 3);

    int bx = (int)floorf(vs.x * (float)R);
    int by = (int)floorf(vs.y * (float)R);
    int bz = (int)floorf(vs.z * (float)R);

    // lanes 0-6: wx[0..6], lanes 7-13: wy, lanes 14-20: wz
    float d = 0.f;
    if (lane < 7)        d = ((float)(bx + lane      - 3) + 0.5f) * INV_R - vs.x;
    else if (lane < 14)  d = ((float)(by + (lane-7)  - 3) + 0.5f) * INV_R - vs.y;
    else if (lane < 21)  d = ((float)(bz + (lane-14) - 3) + 0.5f) * INV_R - vs.z;
    float wd = __expf(-d * d * 200.0f);   // 1/(2*sigma^2), sigma=0.05

    #pragma unroll
    for (int base = 0; base < 343; base += 32) {
        int o  = base + lane;
        int oc = (o < 343) ? o : 342;     // clamp so shuffle idx is sane
        int i = oc / 49;
        int j = (oc / 7) % 7;
        int k = oc % 7;
        float wx = __shfl_sync(0xffffffffu, wd, i);
        float wy = __shfl_sync(0xffffffffu, wd, j + 7);
        float wz = __shfl_sync(0xffffffffu, wd, k + 14);

        int vx = bx + i - 3;
        int vy = by + j - 3;
        int vz = bz + k - 3;
        bool ok = (o < 343) &&
                  (unsigned)vx < R && (unsigned)vy < R && (unsigned)vz < R;
        if (ok) {
            float w = wx * wy * wz;
            int lin = ((b * R + vz) * R + vy) * R + vx;
            float4* ptr = &g_acc[lin];
            asm volatile("red.global.add.v4.f32 [%0], {%1, %2, %3, %4};"
                         :: "l"(ptr), "f"(w), "f"(w * vc.x), "f"(w * vc.y), "f"(w * vc.z)
                         : "memory");
        }
    }
}

// ---------------------------------------------------------------- finalize
// out layout: (B, 3, Z, Y, X); lin-within-batch is already z*R2 + y*R + x.
__global__ void finalize_kernel(float* __restrict__ out) {
    int i = blockIdx.x * blockDim.x + threadIdx.x;
    if (i >= BATCH * R3) return;
    int b = i / R3;
    int l = i - b * R3;

    float4 acc = g_acc[i];
    float  occ = (float)g_occ[i];
    float  sc  = occ / (acc.x + EPS_W);

    float* ob = out + (size_t)b * 3 * R3 + l;
    ob[0]      = acc.y * sc;
    ob[R3]     = acc.z * sc;
    ob[2 * R3] = acc.w * sc;
}

extern "C" void kernel_launch(void* const* d_in, const int* in_sizes, int n_in,
                              void* d_out, int out_size) {
    const float* verts = (const float*)d_in[0];   // smpl_vertices (B, NV, 3)
    const float* code  = (const float*)d_in[1];   // vertex_code   (B, NSURF, 3)
    // d_in[2] face_indices: unused (dead code in reference)
    const int*   tets  = (const int*)d_in[3];     // tet_indices   (NT, 4)
    float*       out   = (float*)d_out;

    void* acc_ptr = nullptr;
    void* occ_ptr = nullptr;
    cudaGetSymbolAddress(&acc_ptr, g_acc);
    cudaGetSymbolAddress(&occ_ptr, g_occ);
    cudaMemsetAsync(acc_ptr, 0, sizeof(float4) * BATCH * R3);
    cudaMemsetAsync(occ_ptr, 0, sizeof(uint8_t) * BATCH * R3);

    const int T = 256;
    tet_setup_kernel<<<(BATCH * NT + T - 1) / T, T>>>(verts, tets);
    tet_test_kernel<<<(BATCH * NT * 125 + T - 1) / T, T>>>();
    splat_kernel<<<(BATCH * NSURF * 32 + T - 1) / T, T>>>(verts, code);
    finalize_kernel<<<(BATCH * R3 + T - 1) / T, T>>>(out);
}